// round 16
// baseline (speedup 1.0000x reference)
#include <cuda_runtime.h>
#include <cuda_fp16.h>

#define N_NODES 100000
#define N_EDGES 3200000
#define NEG_SLOPE 0.2f

// ---------------- scratch (device globals; no allocation allowed) ----------------
__device__ __align__(16) float  g_feat  [(size_t)N_NODES * 128];   // GEMM output (fp32)
__device__ __align__(16) __half g_feat16[(size_t)N_NODES * 128];   // fp16 copy for gather
__device__ __align__(16) float  g_h1    [(size_t)N_NODES * 128];   // layer-1 output
__device__ __align__(16) float  g_el    [N_NODES * 4];
__device__ __align__(16) float  g_er    [N_NODES * 4];
__device__ __align__(16) float  g_invs  [N_NODES * 4];
__device__ __align__(16) float  g_alpha [(size_t)N_EDGES * 4];     // unnormalized softmax * ew
__device__ int   g_csr_src[N_EDGES];
__device__ float g_csr_ew [N_EDGES];
__device__ int   g_deg    [N_NODES];
__device__ int   g_cursor [N_NODES];
__device__ int   g_rowptr [N_NODES + 1];

// ---------------- CSR build ----------------
__global__ void k_init() {
    int i = blockIdx.x * blockDim.x + threadIdx.x;
    if (i < N_NODES) { g_deg[i] = 0; g_cursor[i] = 0; }
}

__global__ void k_hist(const int* __restrict__ dst) {
    int e = blockIdx.x * blockDim.x + threadIdx.x;
    if (e < N_EDGES) atomicAdd(&g_deg[dst[e]], 1);
}

__global__ __launch_bounds__(1024) void k_scan() {
    __shared__ int ssum[1024];
    int t = threadIdx.x;
    const int CH = (N_NODES + 1023) / 1024;   // 98
    int lo = t * CH;
    int hi = lo + CH; if (hi > N_NODES) hi = N_NODES;
    int s = 0;
    for (int i = lo; i < hi; i++) s += g_deg[i];
    ssum[t] = s;
    __syncthreads();
    for (int off = 1; off < 1024; off <<= 1) {
        int v = (t >= off) ? ssum[t - off] : 0;
        __syncthreads();
        ssum[t] += v;
        __syncthreads();
    }
    int run = ssum[t] - s;                    // exclusive prefix
    for (int i = lo; i < hi; i++) { g_rowptr[i] = run; run += g_deg[i]; }
    if (t == 1023) g_rowptr[N_NODES] = ssum[1023];
}

__global__ void k_fill(const int* __restrict__ src, const int* __restrict__ dst,
                       const float* __restrict__ ew) {
    int e = blockIdx.x * blockDim.x + threadIdx.x;
    if (e >= N_EDGES) return;
    int d = dst[e];
    int pos = atomicAdd(&g_cursor[d], 1);
    int slot = g_rowptr[d] + pos;
    g_csr_src[slot] = src[e];
    g_csr_ew[slot]  = ew[e];
}

// ---------------- GEMM: C[N,128] = A[N,128] x W[128,128], fp32, f32x2 FFMA ----------------
__device__ __forceinline__ unsigned long long pack2(float x, float y) {
    unsigned long long r;
    asm("mov.b64 %0, {%1, %2};" : "=l"(r) : "f"(x), "f"(y));
    return r;
}
__device__ __forceinline__ void fma2p(unsigned long long& acc, unsigned long long a2,
                                      unsigned long long b2) {
    asm("fma.rn.f32x2 %0, %1, %2, %0;" : "+l"(acc) : "l"(a2), "l"(b2));
}

__global__ __launch_bounds__(256) void k_gemm(const float* __restrict__ A_ext,
                                              const float* __restrict__ W,
                                              int from_h1) {
    __shared__ float4 As[64 * 32];   // [row][col4 of K], 32 KB
    __shared__ float4 Ws[32 * 32];   // [k][col4 of N],   16 KB
    const float* __restrict__ A = from_h1 ? g_h1 : A_ext;

    int t = threadIdx.x;
    int row0 = blockIdx.x * 64;

    // stage A tile (rows row0..row0+63, full K=128)
    #pragma unroll
    for (int k = 0; k < 8; k++) {
        int ft = t + 256 * k;                 // 0..2047
        int r = row0 + (ft >> 5);
        float4 v = make_float4(0.f, 0.f, 0.f, 0.f);
        if (r < N_NODES) v = reinterpret_cast<const float4*>(A)[(size_t)r * 32 + (ft & 31)];
        As[ft] = v;
    }

    int w = t >> 5, l = t & 31;
    unsigned long long accL[8], accH[8];
    #pragma unroll
    for (int i = 0; i < 8; i++) { accL[i] = 0ull; accH[i] = 0ull; }

    for (int kc = 0; kc < 4; kc++) {
        __syncthreads();
        #pragma unroll
        for (int k = 0; k < 4; k++) {
            int ft = t + 256 * k;             // 0..1023
            Ws[ft] = reinterpret_cast<const float4*>(W)[kc * 1024 + ft];
        }
        __syncthreads();
        const ulonglong2* Wp = reinterpret_cast<const ulonglong2*>(Ws);
        #pragma unroll
        for (int kk4 = 0; kk4 < 8; kk4++) {
            ulonglong2 wv0 = Wp[(kk4 * 4 + 0) * 32 + l];
            ulonglong2 wv1 = Wp[(kk4 * 4 + 1) * 32 + l];
            ulonglong2 wv2 = Wp[(kk4 * 4 + 2) * 32 + l];
            ulonglong2 wv3 = Wp[(kk4 * 4 + 3) * 32 + l];
            #pragma unroll
            for (int i = 0; i < 8; i++) {
                float4 av = As[(w * 8 + i) * 32 + (kc * 8 + kk4)];
                unsigned long long a;
                a = pack2(av.x, av.x); fma2p(accL[i], a, wv0.x); fma2p(accH[i], a, wv0.y);
                a = pack2(av.y, av.y); fma2p(accL[i], a, wv1.x); fma2p(accH[i], a, wv1.y);
                a = pack2(av.z, av.z); fma2p(accL[i], a, wv2.x); fma2p(accH[i], a, wv2.y);
                a = pack2(av.w, av.w); fma2p(accL[i], a, wv3.x); fma2p(accH[i], a, wv3.y);
            }
        }
    }

    #pragma unroll
    for (int i = 0; i < 8; i++) {
        int r = row0 + w * 8 + i;
        if (r >= N_NODES) continue;
        float4 o;
        asm("mov.b64 {%0, %1}, %2;" : "=f"(o.x), "=f"(o.y) : "l"(accL[i]));
        asm("mov.b64 {%0, %1}, %2;" : "=f"(o.z), "=f"(o.w) : "l"(accH[i]));
        reinterpret_cast<float4*>(g_feat)[(size_t)r * 32 + l] = o;
        union { __half2 h[2]; uint2 u; } cv;
        cv.h[0] = __floats2half2_rn(o.x, o.y);
        cv.h[1] = __floats2half2_rn(o.z, o.w);
        *reinterpret_cast<uint2*>(&g_feat16[(size_t)r * 128 + 4 * l]) = cv.u;
    }
}

// ---------------- el/er: per-node, per-head attention dot products ----------------
__global__ __launch_bounds__(256) void k_elr(const float* __restrict__ al,
                                             const float* __restrict__ ar) {
    int n = blockIdx.x * 8 + (threadIdx.x >> 5);
    if (n >= N_NODES) return;
    int l = threadIdx.x & 31;                 // lane l covers dims 4l..4l+3 (head = l>>3)
    float4 f = *reinterpret_cast<const float4*>(&g_feat[(size_t)n * 128 + 4 * l]);
    float4 a = *reinterpret_cast<const float4*>(&al[4 * l]);
    float4 b = *reinterpret_cast<const float4*>(&ar[4 * l]);
    float pl = f.x * a.x + f.y * a.y + f.z * a.z + f.w * a.w;
    float pr = f.x * b.x + f.y * b.y + f.z * b.z + f.w * b.w;
    #pragma unroll
    for (int o = 4; o; o >>= 1) {
        pl += __shfl_xor_sync(0xffffffffu, pl, o);
        pr += __shfl_xor_sync(0xffffffffu, pr, o);
    }
    if ((l & 7) == 0) {
        g_el[n * 4 + (l >> 3)] = pl;
        g_er[n * 4 + (l >> 3)] = pr;
    }
}

// ---------------- attention softmax: warp per dst node, lanes split edges ----------------
__device__ __forceinline__ float lrelu(float x) { return x > 0.f ? x : NEG_SLOPE * x; }

__global__ __launch_bounds__(256) void k_attn() {
    int n = blockIdx.x * 8 + (threadIdx.x >> 5);
    if (n >= N_NODES) return;
    int lane = threadIdx.x & 31;
    int begin = g_rowptr[n], end = g_rowptr[n + 1];
    float4 er4 = *reinterpret_cast<const float4*>(&g_er[n * 4]);

    float m0 = -1e30f, m1 = -1e30f, m2 = -1e30f, m3 = -1e30f;
    for (int i = begin + lane; i < end; i += 32) {
        int s = g_csr_src[i];
        float4 el4 = *reinterpret_cast<const float4*>(&g_el[(size_t)s * 4]);
        m0 = fmaxf(m0, lrelu(el4.x + er4.x));
        m1 = fmaxf(m1, lrelu(el4.y + er4.y));
        m2 = fmaxf(m2, lrelu(el4.z + er4.z));
        m3 = fmaxf(m3, lrelu(el4.w + er4.w));
    }
    #pragma unroll
    for (int o = 16; o; o >>= 1) {
        m0 = fmaxf(m0, __shfl_xor_sync(0xffffffffu, m0, o));
        m1 = fmaxf(m1, __shfl_xor_sync(0xffffffffu, m1, o));
        m2 = fmaxf(m2, __shfl_xor_sync(0xffffffffu, m2, o));
        m3 = fmaxf(m3, __shfl_xor_sync(0xffffffffu, m3, o));
    }

    float s0 = 0.f, s1 = 0.f, s2 = 0.f, s3 = 0.f;
    for (int i = begin + lane; i < end; i += 32) {
        int s = g_csr_src[i];
        float w = g_csr_ew[i];
        float4 el4 = *reinterpret_cast<const float4*>(&g_el[(size_t)s * 4]);
        float p0 = __expf(lrelu(el4.x + er4.x) - m0);
        float p1 = __expf(lrelu(el4.y + er4.y) - m1);
        float p2 = __expf(lrelu(el4.z + er4.z) - m2);
        float p3 = __expf(lrelu(el4.w + er4.w) - m3);
        s0 += p0; s1 += p1; s2 += p2; s3 += p3;
        float4 av = make_float4(p0 * w, p1 * w, p2 * w, p3 * w);
        *reinterpret_cast<float4*>(&g_alpha[(size_t)i * 4]) = av;
    }
    #pragma unroll
    for (int o = 16; o; o >>= 1) {
        s0 += __shfl_xor_sync(0xffffffffu, s0, o);
        s1 += __shfl_xor_sync(0xffffffffu, s1, o);
        s2 += __shfl_xor_sync(0xffffffffu, s2, o);
        s3 += __shfl_xor_sync(0xffffffffu, s3, o);
    }
    if (lane == 0) {
        float4 iv = make_float4(1.f / fmaxf(s0, 1e-20f), 1.f / fmaxf(s1, 1e-20f),
                                1.f / fmaxf(s2, 1e-20f), 1.f / fmaxf(s3, 1e-20f));
        *reinterpret_cast<float4*>(&g_invs[n * 4]) = iv;
    }
}

// ---------------- aggregate: warp per dst node, lanes = feature dims ----------------
__device__ __forceinline__ float elu1(float x) { return x > 0.f ? x : expm1f(x); }

__global__ __launch_bounds__(256) void k_agg(const float* __restrict__ bias,
                                             float* __restrict__ out_ext, int to_h1) {
    int n = blockIdx.x * 8 + (threadIdx.x >> 5);
    if (n >= N_NODES) return;
    int l = threadIdx.x & 31;
    int h = l >> 3;                           // head of dims 4l..4l+3
    int begin = g_rowptr[n], end = g_rowptr[n + 1];

    float ax = 0.f, ay = 0.f, az = 0.f, aw = 0.f;
    #pragma unroll 4
    for (int i = begin; i < end; i++) {
        int s = __ldg(&g_csr_src[i]);
        float4 av = *reinterpret_cast<const float4*>(&g_alpha[(size_t)i * 4]);
        float a = (h & 2) ? ((h & 1) ? av.w : av.z) : ((h & 1) ? av.y : av.x);
        union { __half2 h2[2]; uint2 u; } cv;
        cv.u = *reinterpret_cast<const uint2*>(&g_feat16[(size_t)s * 128 + 4 * l]);
        float2 f01 = __half22float2(cv.h2[0]);
        float2 f23 = __half22float2(cv.h2[1]);
        ax = fmaf(a, f01.x, ax);
        ay = fmaf(a, f01.y, ay);
        az = fmaf(a, f23.x, az);
        aw = fmaf(a, f23.y, aw);
    }

    float4 iv = *reinterpret_cast<const float4*>(&g_invs[n * 4]);
    float inv = (h & 2) ? ((h & 1) ? iv.w : iv.z) : ((h & 1) ? iv.y : iv.x);
    float4 b = *reinterpret_cast<const float4*>(&bias[4 * l]);
    float4 o;
    o.x = elu1(ax * inv + b.x);
    o.y = elu1(ay * inv + b.y);
    o.z = elu1(az * inv + b.z);
    o.w = elu1(aw * inv + b.w);
    float* out = to_h1 ? g_h1 : out_ext;
    *reinterpret_cast<float4*>(&out[(size_t)n * 128 + 4 * l]) = o;
}

// ---------------- launch ----------------
extern "C" void kernel_launch(void* const* d_in, const int* in_sizes, int n_in,
                              void* d_out, int out_size) {
    const float* in_feat = (const float*)d_in[0];
    const float* ew      = (const float*)d_in[1];
    const int*   src     = (const int*)  d_in[2];
    const int*   dst     = (const int*)  d_in[3];
    const float* W0      = (const float*)d_in[4];
    const float* al0     = (const float*)d_in[5];
    const float* ar0     = (const float*)d_in[6];
    const float* b0      = (const float*)d_in[7];
    const float* W1      = (const float*)d_in[8];
    const float* al1     = (const float*)d_in[9];
    const float* ar1     = (const float*)d_in[10];
    const float* b1      = (const float*)d_in[11];
    float* out = (float*)d_out;

    const int NB_N  = (N_NODES + 255) / 256;
    const int NB_E  = (N_EDGES + 255) / 256;
    const int NB_W  = (N_NODES + 7) / 8;      // warp-per-node kernels
    const int NB_G  = (N_NODES + 63) / 64;    // GEMM

    // CSR build (same graph for both layers)
    k_init<<<NB_N, 256>>>();
    k_hist<<<NB_E, 256>>>(dst);
    k_scan<<<1, 1024>>>();
    k_fill<<<NB_E, 256>>>(src, dst, ew);

    // layer 1
    k_gemm<<<NB_G, 256>>>(in_feat, W0, 0);
    k_elr <<<NB_W, 256>>>(al0, ar0);
    k_attn<<<NB_W, 256>>>();
    k_agg <<<NB_W, 256>>>(b0, nullptr, 1);

    // layer 2
    k_gemm<<<NB_G, 256>>>(nullptr, W1, 1);
    k_elr <<<NB_W, 256>>>(al1, ar1);
    k_attn<<<NB_W, 256>>>();
    k_agg <<<NB_W, 256>>>(b1, out, 0);
}